// round 3
// baseline (speedup 1.0000x reference)
#include <cuda_runtime.h>

// WENO Black-Scholes explicit time-stepper.
// M=80 grid cells (81 nodes), 26 Euler steps, fixed per-point WENO weights.
// Single block / single warp; each lane owns rows {lane, lane+32, lane+64}.
// State double-buffered in shared memory; 2 __syncwarp() per step.

#define M_GRID 80
#define N_STEPS 26

__global__ void __launch_bounds__(32, 1)
weno_bs_kernel(const float* __restrict__ om5,   // (80,3) row-major
               const float* __restrict__ om6,   // (79,3) row-major
               float* __restrict__ out)         // 81 floats
{
    // up layout: up[2+k] = u[k], k=0..M. up[0]=up[1]=0 (left ghosts, constant).
    // Right ghost up[83] = 2*u[M]-u[M-1] is computed in registers by the two
    // lanes that need it (reference never reads up[84]).
    __shared__ float upbuf[2][M_GRID + 5];
    __shared__ float uh[M_GRID];   // uhat, size M

    const int lane = threadIdx.x;

    const float H   = 0.09375f;            // exact in fp32
    const float H2  = 0.0087890625f;       // H*H, exact
    const float DT  = (float)(1.0 / 26.0);
    const float S_R = 50.0f * expf(1.5f);  // S[M]

    // ---- init u0 into both buffers ----
    for (int i = lane; i <= M_GRID; i += 32) {
        float x = -6.0f + (float)i * 0.09375f;          // exact
        float v = fmaxf(50.0f * expf(x) - 50.0f, 0.0f); // u0[0] == 0 exactly
        upbuf[0][2 + i] = v;
        upbuf[1][2 + i] = v;
    }
    if (lane < 2) {           // left ghosts: constant 0 in both buffers
        upbuf[0][lane] = 0.0f;
        upbuf[1][lane] = 0.0f;
    }

    // ---- load per-row weights into registers ----
    const int r0 = lane, r1 = lane + 32, r2 = lane + 64;
    float w5a0, w5a1, w5a2, w5b0, w5b1, w5b2, w5c0 = 0.f, w5c1 = 0.f, w5c2 = 0.f;
    float w6a0, w6a1, w6a2, w6b0, w6b1, w6b2, w6c0 = 0.f, w6c1 = 0.f, w6c2 = 0.f;
    w5a0 = om5[3 * r0]; w5a1 = om5[3 * r0 + 1]; w5a2 = om5[3 * r0 + 2];
    w5b0 = om5[3 * r1]; w5b1 = om5[3 * r1 + 1]; w5b2 = om5[3 * r1 + 2];
    if (r2 < M_GRID) { w5c0 = om5[3 * r2]; w5c1 = om5[3 * r2 + 1]; w5c2 = om5[3 * r2 + 2]; }
    w6a0 = om6[3 * r0]; w6a1 = om6[3 * r0 + 1]; w6a2 = om6[3 * r0 + 2];
    if (r1 < M_GRID - 1) { w6b0 = om6[3 * r1]; w6b1 = om6[3 * r1 + 1]; w6b2 = om6[3 * r1 + 2]; }
    if (r2 < M_GRID - 1) { w6c0 = om6[3 * r2]; w6c1 = om6[3 * r2 + 1]; w6c2 = om6[3 * r2 + 2]; }

    float t = 0.0f;
    int cur = 0;

    __syncwarp();

    for (int s = 0; s < N_STEPS; ++s) {
        const float* __restrict__ up = upbuf[cur];
        float* __restrict__ nx = upbuf[cur ^ 1];

        // ---- phase 1: uhat[i], i = 0..M-1, uses up[i..i+4] ----
        {
            // row r0 (i = lane, 0..31)
            float um2 = up[r0], um1 = up[r0 + 1], uc = up[r0 + 2],
                  up1 = up[r0 + 3], up2 = up[r0 + 4];
            float f0 = (2.0f * um2 - 7.0f * um1 + 11.0f * uc) / 6.0f;
            float f1 = (-um1 + 5.0f * uc + 2.0f * up1) / 6.0f;
            float f2 = (2.0f * uc + 5.0f * up1 - up2) / 6.0f;
            uh[r0] = w5a0 * f0 + w5a1 * f1 + w5a2 * f2;
        }
        {
            // row r1 (i = lane+32, 32..63)
            float um2 = up[r1], um1 = up[r1 + 1], uc = up[r1 + 2],
                  up1 = up[r1 + 3], up2 = up[r1 + 4];
            float f0 = (2.0f * um2 - 7.0f * um1 + 11.0f * uc) / 6.0f;
            float f1 = (-um1 + 5.0f * uc + 2.0f * up1) / 6.0f;
            float f2 = (2.0f * uc + 5.0f * up1 - up2) / 6.0f;
            uh[r1] = w5b0 * f0 + w5b1 * f1 + w5b2 * f2;
        }
        if (r2 < M_GRID) {
            // row r2 (i = lane+64, 64..79). i=79 needs up[83] = 2*u[M]-u[M-1].
            float um2 = up[r2], um1 = up[r2 + 1], uc = up[r2 + 2],
                  up1 = up[r2 + 3];
            float up2v = (r2 + 4 <= M_GRID + 2) ? up[r2 + 4]
                                                : (2.0f * up[M_GRID + 2] - up[M_GRID + 1]);
            float f0 = (2.0f * um2 - 7.0f * um1 + 11.0f * uc) / 6.0f;
            float f1 = (-um1 + 5.0f * uc + 2.0f * up1) / 6.0f;
            float f2 = (2.0f * uc + 5.0f * up1 - up2v) / 6.0f;
            uh[r2] = w5c0 * f0 + w5c1 * f1 + w5c2 * f2;
        }
        __syncwarp();

        // ---- phase 2: j = 0..M-2, write nx[3+j] ----
        t = t + DT;
        {
            // j = r0 (0..31)
            int j = r0;
            float ux  = (uh[j + 1] - uh[j]) / H;
            float dm2 = up[1 + j], dm1 = up[2 + j], dc = up[3 + j],
                  dp1 = up[4 + j], dp2 = up[5 + j];
            float c0 = dm2 - 2.0f * dm1 + dc;
            float c1 = dm1 - 2.0f * dc + dp1;
            float c2 = dc - 2.0f * dp1 + dp2;
            float uxx = (w6a0 * c0 + w6a1 * c1 + w6a2 * c2) / H2;
            float du  = 0.045f * uxx + 0.055f * ux - 0.1f * dc;
            nx[3 + j] = dc + DT * du;
        }
        if (r1 < M_GRID - 1) {
            // j = r1 (32..63)
            int j = r1;
            float ux  = (uh[j + 1] - uh[j]) / H;
            float dm2 = up[1 + j], dm1 = up[2 + j], dc = up[3 + j],
                  dp1 = up[4 + j], dp2 = up[5 + j];
            float c0 = dm2 - 2.0f * dm1 + dc;
            float c1 = dm1 - 2.0f * dc + dp1;
            float c2 = dc - 2.0f * dp1 + dp2;
            float uxx = (w6b0 * c0 + w6b1 * c1 + w6b2 * c2) / H2;
            float du  = 0.045f * uxx + 0.055f * ux - 0.1f * dc;
            nx[3 + j] = dc + DT * du;
        }
        if (r2 < M_GRID - 1) {
            // j = r2 (64..78). j=78 needs dp2 = up[83] (register ghost).
            int j = r2;
            float ux  = (uh[j + 1] - uh[j]) / H;
            float dm2 = up[1 + j], dm1 = up[2 + j], dc = up[3 + j],
                  dp1 = up[4 + j];
            float dp2 = (5 + j <= M_GRID + 2) ? up[5 + j]
                                              : (2.0f * up[M_GRID + 2] - up[M_GRID + 1]);
            float c0 = dm2 - 2.0f * dm1 + dc;
            float c1 = dm1 - 2.0f * dc + dp1;
            float c2 = dc - 2.0f * dp1 + dp2;
            float uxx = (w6c0 * c0 + w6c1 * c1 + w6c2 * c2) / H2;
            float du  = 0.045f * uxx + 0.055f * ux - 0.1f * dc;
            nx[3 + j] = dc + DT * du;
        }
        if (lane == 0) {
            nx[2] = 0.0f;                                      // un[0] = 0
            nx[2 + M_GRID] = S_R - 50.0f * expf(-0.1f * t);    // right BC
        }
        __syncwarp();
        cur ^= 1;
    }

    // ---- write result ----
    const float* uf = upbuf[cur];
    for (int i = lane; i <= M_GRID; i += 32)
        out[i] = uf[2 + i];
}

extern "C" void kernel_launch(void* const* d_in, const int* in_sizes, int n_in,
                              void* d_out, int out_size) {
    (void)in_sizes; (void)n_in; (void)out_size;
    const float* om5 = (const float*)d_in[0];   // omegas5 (80,3)
    const float* om6 = (const float*)d_in[1];   // omegas6 (79,3)
    float* out = (float*)d_out;                 // 81 floats
    weno_bs_kernel<<<1, 32>>>(om5, om6, out);
}

// round 4
// speedup vs baseline: 1.0054x; 1.0054x over previous
#include <cuda_runtime.h>

// WENO Black-Scholes explicit time-stepper.
// M=80 grid cells (81 nodes), 26 Euler steps, fixed per-point WENO weights.
// Single block / single warp; each lane owns rows {lane, lane+32, lane+64}.
// State double-buffered in shared memory; 2 __syncwarp() per step.

#define M_GRID 80
#define N_STEPS 26

__global__ void __launch_bounds__(32, 1)
weno_bs_kernel(const float* __restrict__ om5,   // (80,3) row-major
               const float* __restrict__ om6,   // (79,3) row-major
               float* __restrict__ out)         // 81 floats
{
    // up layout: up[2+k] = u[k], k=0..M. up[0]=up[1]=0 (left ghosts, constant).
    // Right ghost up[83] = 2*u[M]-u[M-1] is computed in registers by the two
    // lanes that need it (reference never reads up[84]).
    __shared__ float upbuf[2][M_GRID + 5];
    __shared__ float uh[M_GRID];   // uhat, size M

    const int lane = threadIdx.x;

    const float H   = 0.09375f;            // exact in fp32
    const float H2  = 0.0087890625f;       // H*H, exact
    const float DT  = (float)(1.0 / 26.0);
    const float S_R = 50.0f * expf(1.5f);  // S[M]

    // ---- init u0 into both buffers ----
    for (int i = lane; i <= M_GRID; i += 32) {
        float x = -6.0f + (float)i * 0.09375f;          // exact
        float v = fmaxf(50.0f * expf(x) - 50.0f, 0.0f); // u0[0] == 0 exactly
        upbuf[0][2 + i] = v;
        upbuf[1][2 + i] = v;
    }
    if (lane < 2) {           // left ghosts: constant 0 in both buffers
        upbuf[0][lane] = 0.0f;
        upbuf[1][lane] = 0.0f;
    }

    // ---- load per-row weights into registers ----
    const int r0 = lane, r1 = lane + 32, r2 = lane + 64;
    float w5a0, w5a1, w5a2, w5b0, w5b1, w5b2, w5c0 = 0.f, w5c1 = 0.f, w5c2 = 0.f;
    float w6a0, w6a1, w6a2, w6b0, w6b1, w6b2, w6c0 = 0.f, w6c1 = 0.f, w6c2 = 0.f;
    w5a0 = om5[3 * r0]; w5a1 = om5[3 * r0 + 1]; w5a2 = om5[3 * r0 + 2];
    w5b0 = om5[3 * r1]; w5b1 = om5[3 * r1 + 1]; w5b2 = om5[3 * r1 + 2];
    if (r2 < M_GRID) { w5c0 = om5[3 * r2]; w5c1 = om5[3 * r2 + 1]; w5c2 = om5[3 * r2 + 2]; }
    w6a0 = om6[3 * r0]; w6a1 = om6[3 * r0 + 1]; w6a2 = om6[3 * r0 + 2];
    if (r1 < M_GRID - 1) { w6b0 = om6[3 * r1]; w6b1 = om6[3 * r1 + 1]; w6b2 = om6[3 * r1 + 2]; }
    if (r2 < M_GRID - 1) { w6c0 = om6[3 * r2]; w6c1 = om6[3 * r2 + 1]; w6c2 = om6[3 * r2 + 2]; }

    float t = 0.0f;
    int cur = 0;

    __syncwarp();

    for (int s = 0; s < N_STEPS; ++s) {
        const float* __restrict__ up = upbuf[cur];
        float* __restrict__ nx = upbuf[cur ^ 1];

        // ---- phase 1: uhat[i], i = 0..M-1, uses up[i..i+4] ----
        {
            // row r0 (i = lane, 0..31)
            float um2 = up[r0], um1 = up[r0 + 1], uc = up[r0 + 2],
                  up1 = up[r0 + 3], up2 = up[r0 + 4];
            float f0 = (2.0f * um2 - 7.0f * um1 + 11.0f * uc) / 6.0f;
            float f1 = (-um1 + 5.0f * uc + 2.0f * up1) / 6.0f;
            float f2 = (2.0f * uc + 5.0f * up1 - up2) / 6.0f;
            uh[r0] = w5a0 * f0 + w5a1 * f1 + w5a2 * f2;
        }
        {
            // row r1 (i = lane+32, 32..63)
            float um2 = up[r1], um1 = up[r1 + 1], uc = up[r1 + 2],
                  up1 = up[r1 + 3], up2 = up[r1 + 4];
            float f0 = (2.0f * um2 - 7.0f * um1 + 11.0f * uc) / 6.0f;
            float f1 = (-um1 + 5.0f * uc + 2.0f * up1) / 6.0f;
            float f2 = (2.0f * uc + 5.0f * up1 - up2) / 6.0f;
            uh[r1] = w5b0 * f0 + w5b1 * f1 + w5b2 * f2;
        }
        if (r2 < M_GRID) {
            // row r2 (i = lane+64, 64..79). i=79 needs up[83] = 2*u[M]-u[M-1].
            float um2 = up[r2], um1 = up[r2 + 1], uc = up[r2 + 2],
                  up1 = up[r2 + 3];
            float up2v = (r2 + 4 <= M_GRID + 2) ? up[r2 + 4]
                                                : (2.0f * up[M_GRID + 2] - up[M_GRID + 1]);
            float f0 = (2.0f * um2 - 7.0f * um1 + 11.0f * uc) / 6.0f;
            float f1 = (-um1 + 5.0f * uc + 2.0f * up1) / 6.0f;
            float f2 = (2.0f * uc + 5.0f * up1 - up2v) / 6.0f;
            uh[r2] = w5c0 * f0 + w5c1 * f1 + w5c2 * f2;
        }
        __syncwarp();

        // ---- phase 2: j = 0..M-2, write nx[3+j] ----
        t = t + DT;
        {
            // j = r0 (0..31)
            int j = r0;
            float ux  = (uh[j + 1] - uh[j]) / H;
            float dm2 = up[1 + j], dm1 = up[2 + j], dc = up[3 + j],
                  dp1 = up[4 + j], dp2 = up[5 + j];
            float c0 = dm2 - 2.0f * dm1 + dc;
            float c1 = dm1 - 2.0f * dc + dp1;
            float c2 = dc - 2.0f * dp1 + dp2;
            float uxx = (w6a0 * c0 + w6a1 * c1 + w6a2 * c2) / H2;
            float du  = 0.045f * uxx + 0.055f * ux - 0.1f * dc;
            nx[3 + j] = dc + DT * du;
        }
        if (r1 < M_GRID - 1) {
            // j = r1 (32..63)
            int j = r1;
            float ux  = (uh[j + 1] - uh[j]) / H;
            float dm2 = up[1 + j], dm1 = up[2 + j], dc = up[3 + j],
                  dp1 = up[4 + j], dp2 = up[5 + j];
            float c0 = dm2 - 2.0f * dm1 + dc;
            float c1 = dm1 - 2.0f * dc + dp1;
            float c2 = dc - 2.0f * dp1 + dp2;
            float uxx = (w6b0 * c0 + w6b1 * c1 + w6b2 * c2) / H2;
            float du  = 0.045f * uxx + 0.055f * ux - 0.1f * dc;
            nx[3 + j] = dc + DT * du;
        }
        if (r2 < M_GRID - 1) {
            // j = r2 (64..78). j=78 needs dp2 = up[83] (register ghost).
            int j = r2;
            float ux  = (uh[j + 1] - uh[j]) / H;
            float dm2 = up[1 + j], dm1 = up[2 + j], dc = up[3 + j],
                  dp1 = up[4 + j];
            float dp2 = (5 + j <= M_GRID + 2) ? up[5 + j]
                                              : (2.0f * up[M_GRID + 2] - up[M_GRID + 1]);
            float c0 = dm2 - 2.0f * dm1 + dc;
            float c1 = dm1 - 2.0f * dc + dp1;
            float c2 = dc - 2.0f * dp1 + dp2;
            float uxx = (w6c0 * c0 + w6c1 * c1 + w6c2 * c2) / H2;
            float du  = 0.045f * uxx + 0.055f * ux - 0.1f * dc;
            nx[3 + j] = dc + DT * du;
        }
        if (lane == 0) {
            nx[2] = 0.0f;                                      // un[0] = 0
            nx[2 + M_GRID] = S_R - 50.0f * expf(-0.1f * t);    // right BC
        }
        __syncwarp();
        cur ^= 1;
    }

    // ---- write result ----
    const float* uf = upbuf[cur];
    for (int i = lane; i <= M_GRID; i += 32)
        out[i] = uf[2 + i];
}

extern "C" void kernel_launch(void* const* d_in, const int* in_sizes, int n_in,
                              void* d_out, int out_size) {
    (void)in_sizes; (void)n_in; (void)out_size;
    const float* om5 = (const float*)d_in[0];   // omegas5 (80,3)
    const float* om6 = (const float*)d_in[1];   // omegas6 (79,3)
    float* out = (float*)d_out;                 // 81 floats
    weno_bs_kernel<<<1, 32>>>(om5, om6, out);
}

// round 5
// speedup vs baseline: 5.3429x; 5.3143x over previous
#include <cuda_runtime.h>

// WENO Black-Scholes explicit stepper, M=80 (81 nodes), 26 Euler steps.
// Pure register + warp-shuffle implementation: no shared memory, no barriers.
// Lane l owns u[l] (a), u[l+32] (b), u[l+64] (c, lanes 0..16; lane 16 = node 80).

#define FULLM 0xFFFFFFFFu
#define N_STEPS 26

__global__ void __launch_bounds__(32, 1)
weno_bs_kernel(const float* __restrict__ om5,   // (80,3) row-major
               const float* __restrict__ om6,   // (79,3) row-major
               float* __restrict__ out)         // 81 floats
{
    const int l = threadIdx.x;

    const float INV6  = 1.0f / 6.0f;
    const float INVH  = 1.0f / 0.09375f;
    const float INVH2 = 1.0f / 0.0087890625f;       // 1/H^2, H^2 exact
    const float DT    = (float)(1.0 / 26.0);

    // ---- init u0: u0[i] = max(50*exp(x_i)-50, 0), x_i = -6 + i*H (H exact) ----
    float a = fmaxf(50.0f * expf(fmaf((float)l,        0.09375f, -6.0f)) - 50.0f, 0.0f);
    float b = fmaxf(50.0f * expf(fmaf((float)(l + 32), 0.09375f, -6.0f)) - 50.0f, 0.0f);
    float c = (l <= 16)
            ? fmaxf(50.0f * expf(fmaf((float)(l + 64), 0.09375f, -6.0f)) - 50.0f, 0.0f)
            : 0.0f;

    // ---- per-lane weights in registers ----
    float w5a0 = om5[3*l+0],      w5a1 = om5[3*l+1],      w5a2 = om5[3*l+2];
    float w5b0 = om5[3*(l+32)+0], w5b1 = om5[3*(l+32)+1], w5b2 = om5[3*(l+32)+2];
    float w5c0 = 0.f, w5c1 = 0.f, w5c2 = 0.f;
    if (l < 16) { w5c0 = om5[3*(l+64)+0]; w5c1 = om5[3*(l+64)+1]; w5c2 = om5[3*(l+64)+2]; }
    float w6a0 = 0.f, w6a1 = 0.f, w6a2 = 0.f;           // node k=l needs row k-1
    if (l >= 1) { w6a0 = om6[3*(l-1)+0]; w6a1 = om6[3*(l-1)+1]; w6a2 = om6[3*(l-1)+2]; }
    float w6b0 = om6[3*(l+31)+0], w6b1 = om6[3*(l+31)+1], w6b2 = om6[3*(l+31)+2];
    float w6c0 = 0.f, w6c1 = 0.f, w6c2 = 0.f;
    if (l < 16) { w6c0 = om6[3*(l+63)+0]; w6c1 = om6[3*(l+63)+1]; w6c2 = om6[3*(l+63)+2]; }

    // ---- precompute the 26 right-BC values, one per lane; broadcast per step ----
    float bcv = 50.0f * expf(1.5f) - 50.0f * expf(-0.1f * DT * (float)(l + 1));

    const int lp1 = (l + 1) & 31, lp2 = (l + 2) & 31;
    const int lm1 = (l - 1) & 31, lm2 = (l - 2) & 31;
    const bool ge1 = (l >= 1), ge2 = (l >= 2);
    const bool lt30 = (l < 30), lt31 = (l < 31);

    #pragma unroll 1
    for (int s = 0; s < N_STEPS; ++s) {
        // ---- neighbor gather via shuffles (all independent) ----
        float ap  = __shfl_sync(FULLM, a, lp1);
        float bp  = __shfl_sync(FULLM, b, lp1);
        float cp  = __shfl_sync(FULLM, c, lp1);
        float ap2 = __shfl_sync(FULLM, a, lp2);
        float bp2 = __shfl_sync(FULLM, b, lp2);
        float cp2 = __shfl_sync(FULLM, c, lp2);
        float am  = __shfl_sync(FULLM, a, lm1);
        float bm  = __shfl_sync(FULLM, b, lm1);
        float cm  = __shfl_sync(FULLM, c, lm1);
        float am2 = __shfl_sync(FULLM, a, lm2);
        float bm2 = __shfl_sync(FULLM, b, lm2);
        float cm2 = __shfl_sync(FULLM, c, lm2);
        float u80 = __shfl_sync(FULLM, c, 16);
        float u79 = __shfl_sync(FULLM, c, 15);
        float gR  = 2.0f * u80 - u79;                 // right ghost u[81]

        // slot-wise shifted values (predicated cross-slot stitching)
        float aP1 = lt31 ? ap  : bp;                  // u[l+1]
        float bP1 = lt31 ? bp  : cp;                  // u[l+33]
        float cP1 = cp;                               // u[l+65] (valid l<=15)
        float aP2 = lt30 ? ap2 : bp2;                 // u[l+2]
        float bP2 = lt30 ? bp2 : cp2;                 // u[l+34]
        float cP2 = (l == 15) ? gR : cp2;             // u[l+66]; l=15 -> u[81]
        float aM1 = ge1 ? am  : 0.0f;                 // u[l-1]; left ghost = 0
        float bM1 = ge1 ? bm  : am;                   // u[l+31]
        float cM1 = ge1 ? cm  : bm;                   // u[l+63]
        float aM2 = ge2 ? am2 : 0.0f;                 // u[l-2]
        float bM2 = ge2 ? bm2 : am2;                  // u[l+30]
        float cM2 = ge2 ? cm2 : bm2;                  // u[l+62]

        // ---- WENO flux reconstruction uhat[i], i = owned node index ----
        float f0, f1, f2;
        f0 = (2.0f*aM2 - 7.0f*aM1 + 11.0f*a) * INV6;
        f1 = (-aM1 + 5.0f*a + 2.0f*aP1) * INV6;
        f2 = (2.0f*a + 5.0f*aP1 - aP2) * INV6;
        float ha = w5a0*f0 + w5a1*f1 + w5a2*f2;
        f0 = (2.0f*bM2 - 7.0f*bM1 + 11.0f*b) * INV6;
        f1 = (-bM1 + 5.0f*b + 2.0f*bP1) * INV6;
        f2 = (2.0f*b + 5.0f*bP1 - bP2) * INV6;
        float hb = w5b0*f0 + w5b1*f1 + w5b2*f2;
        f0 = (2.0f*cM2 - 7.0f*cM1 + 11.0f*c) * INV6;
        f1 = (-cM1 + 5.0f*c + 2.0f*cP1) * INV6;
        f2 = (2.0f*c + 5.0f*cP1 - cP2) * INV6;
        float hc = w5c0*f0 + w5c1*f1 + w5c2*f2;       // valid l<=15

        // uhat[k-1]
        float ham = __shfl_sync(FULLM, ha, lm1);
        float hbm = __shfl_sync(FULLM, hb, lm1);
        float hcm = __shfl_sync(FULLM, hc, lm1);
        float haM1 = ham;                             // used only l>=1
        float hbM1 = ge1 ? hbm : ham;                 // l=0: uhat[31]
        float hcM1 = ge1 ? hcm : hbm;                 // l=0: uhat[63]

        // ---- Euler update: du = 0.045*uxx + 0.055*ux - 0.1*u ----
        float ux, c0, c1, c2, uxx, du;
        ux  = (ha - haM1) * INVH;
        c0  = aM2 - 2.0f*aM1 + a;
        c1  = aM1 - 2.0f*a + aP1;
        c2  = a - 2.0f*aP1 + aP2;
        uxx = (w6a0*c0 + w6a1*c1 + w6a2*c2) * INVH2;
        du  = 0.045f*uxx + 0.055f*ux - 0.1f*a;
        float na = a + DT * du;

        ux  = (hb - hbM1) * INVH;
        c0  = bM2 - 2.0f*bM1 + b;
        c1  = bM1 - 2.0f*b + bP1;
        c2  = b - 2.0f*bP1 + bP2;
        uxx = (w6b0*c0 + w6b1*c1 + w6b2*c2) * INVH2;
        du  = 0.045f*uxx + 0.055f*ux - 0.1f*b;
        float nb = b + DT * du;

        ux  = (hc - hcM1) * INVH;
        c0  = cM2 - 2.0f*cM1 + c;
        c1  = cM1 - 2.0f*c + cP1;
        c2  = c - 2.0f*cP1 + cP2;
        uxx = (w6c0*c0 + w6c1*c1 + w6c2*c2) * INVH2;
        du  = 0.045f*uxx + 0.055f*ux - 0.1f*c;
        float nc = c + DT * du;

        float bcs = __shfl_sync(FULLM, bcv, s);       // BC(t_{s+1})

        a = ge1 ? na : 0.0f;                          // node 0 pinned to 0
        b = nb;
        c = (l < 16) ? nc : ((l == 16) ? bcs : c);    // node 80 = BC
    }

    // ---- write result ----
    out[l]      = a;
    out[l + 32] = b;
    if (l <= 16) out[l + 64] = c;
}

extern "C" void kernel_launch(void* const* d_in, const int* in_sizes, int n_in,
                              void* d_out, int out_size) {
    (void)in_sizes; (void)n_in; (void)out_size;
    const float* om5 = (const float*)d_in[0];   // omegas5 (80,3)
    const float* om6 = (const float*)d_in[1];   // omegas6 (79,3)
    float* out = (float*)d_out;                 // 81 floats
    weno_bs_kernel<<<1, 32>>>(om5, om6, out);
}

// round 6
// speedup vs baseline: 7.2271x; 1.3527x over previous
#include <cuda_runtime.h>

// WENO Black-Scholes stepper, M=80 (81 nodes), 26 Euler steps.
// Each timestep is affine in u: u_{n+1}[k] = sum_{j=-3}^{+2} C_j[k] * u[k+j],
// with C precomputed once from the (fixed) WENO weights. Lane l owns nodes
// {3l, 3l+1, 3l+2} (lanes 0..26); 5 shuffles + 18 FMAs per step, no smem.

#define N_STEPS 26
#define FULLM 0xFFFFFFFFu

// Fused 6-tap coefficients for node k over u[k-3..k+2].
// p = w5 row k, q = w5 row k-1, r = w6 row k-1.
__device__ __forceinline__ void make_coef(const float* p, const float* q,
                                          const float* r, float g1, float g2,
                                          float decay, float* C)
{
    const float i6 = 1.0f / 6.0f;
    // uhat[k] taps over u[k-2..k+2]
    float A_2 = (2.0f * p[0]) * i6;
    float A_1 = (-7.0f * p[0] - p[1]) * i6;
    float A0  = (11.0f * p[0] + 5.0f * p[1] + 2.0f * p[2]) * i6;
    float A1  = (2.0f * p[1] + 5.0f * p[2]) * i6;
    float A2  = (-p[2]) * i6;
    // uhat[k-1] taps over u[k-3..k+1]
    float B_3 = (2.0f * q[0]) * i6;
    float B_2 = (-7.0f * q[0] - q[1]) * i6;
    float B_1 = (11.0f * q[0] + 5.0f * q[1] + 2.0f * q[2]) * i6;
    float B0  = (2.0f * q[1] + 5.0f * q[2]) * i6;
    float B1  = (-q[2]) * i6;
    // C[j+3] = g1*(A[j]-B[j]) + g2*Xuxx[j] (+decay at j=0)
    C[0] = -g1 * B_3;
    C[1] = g1 * (A_2 - B_2) + g2 * r[0];
    C[2] = g1 * (A_1 - B_1) + g2 * (r[1] - 2.0f * r[0]);
    C[3] = g1 * (A0 - B0)   + g2 * (r[0] - 2.0f * r[1] + r[2]) + decay;
    C[4] = g1 * (A1 - B1)   + g2 * (r[1] - 2.0f * r[2]);
    C[5] = g1 * A2          + g2 * r[2];
}

__global__ void __launch_bounds__(32, 1)
weno_bs_kernel(const float* __restrict__ om5,   // (80,3) row-major
               const float* __restrict__ om6,   // (79,3) row-major
               float* __restrict__ out)         // 81 floats
{
    const int l = threadIdx.x;
    const bool act = (l <= 26);

    const float H     = 0.09375f;                 // exact in fp32
    const float DT    = (float)(1.0 / 26.0);
    const float g1    = DT * 0.055f / H;          // DT*ADV/H
    const float g2    = DT * 0.045f / (H * H);    // DT*0.5*sigma^2/H^2
    const float decay = 1.0f - DT * 0.1f;

    // ---- init u0 ----
    float a = 0.f, b = 0.f, c = 0.f;
    if (act) {
        a = fmaxf(50.0f * expf(fmaf((float)(3 * l),     H, -6.0f)) - 50.0f, 0.0f);
        b = fmaxf(50.0f * expf(fmaf((float)(3 * l + 1), H, -6.0f)) - 50.0f, 0.0f);
        c = fmaxf(50.0f * expf(fmaf((float)(3 * l + 2), H, -6.0f)) - 50.0f, 0.0f);
    }

    // ---- load weight rows (guarded; out-of-range rows -> 0, nodes 0/80 are
    //      pinned/BC so their garbage coefficients are never used) ----
    float p[4][3] = {{0}}, r[3][3] = {{0}};
    if (act) {
        #pragma unroll
        for (int j = 0; j < 4; ++j) {
            int row = 3 * l - 1 + j;               // w5 rows 3l-1 .. 3l+2
            if (row >= 0 && row < 80) {
                p[j][0] = om5[3 * row]; p[j][1] = om5[3 * row + 1]; p[j][2] = om5[3 * row + 2];
            }
        }
        #pragma unroll
        for (int j = 0; j < 3; ++j) {
            int row = 3 * l - 1 + j;               // w6 rows 3l-1 .. 3l+1
            if (row >= 0 && row < 79) {
                r[j][0] = om6[3 * row]; r[j][1] = om6[3 * row + 1]; r[j][2] = om6[3 * row + 2];
            }
        }
    }

    // ---- fused per-node coefficients (computed once) ----
    float Ca[6] = {0}, Cb[6] = {0}, Cc[6] = {0};
    if (act) {
        make_coef(p[1], p[0], r[0], g1, g2, decay, Ca);  // node 3l
        make_coef(p[2], p[1], r[1], g1, g2, decay, Cb);  // node 3l+1
        make_coef(p[3], p[2], r[2], g1, g2, decay, Cc);  // node 3l+2
    }

    // ---- right-BC recurrence: bc(t_n) = S_R - 50*exp(-0.1*t_n) ----
    float e = 1.0f;
    const float E0  = expf(-0.1f * DT);
    const float S_R = 50.0f * expf(1.5f);

    // ---- time stepping ----
    #pragma unroll
    for (int s = 0; s < N_STEPS; ++s) {
        float am = __shfl_up_sync(FULLM, a, 1);    // u[3l-3]
        float bm = __shfl_up_sync(FULLM, b, 1);    // u[3l-2]
        float cm = __shfl_up_sync(FULLM, c, 1);    // u[3l-1]
        float ap = __shfl_down_sync(FULLM, a, 1);  // u[3l+3]
        float bp = __shfl_down_sync(FULLM, b, 1);  // u[3l+4]
        if (l == 0)  { am = 0.f; bm = 0.f; cm = 0.f; }   // left ghosts = 0
        if (l == 26) { ap = 2.0f * c - b; }              // u[81] = 2u[80]-u[79]
        e *= E0;

        float na = Ca[0]*am + Ca[1]*bm + Ca[2]*cm + Ca[3]*a  + Ca[4]*b  + Ca[5]*c;
        float nb = Cb[0]*bm + Cb[1]*cm + Cb[2]*a  + Cb[3]*b  + Cb[4]*c  + Cb[5]*ap;
        float nc = Cc[0]*cm + Cc[1]*a  + Cc[2]*b  + Cc[3]*c  + Cc[4]*ap + Cc[5]*bp;

        a = (l == 0)  ? 0.0f : na;                       // node 0 pinned
        b = nb;
        c = (l == 26) ? fmaf(-50.0f, e, S_R) : nc;       // node 80 = BC(t_{n+1})
    }

    // ---- write result ----
    if (act) {
        out[3 * l]     = a;
        out[3 * l + 1] = b;
        out[3 * l + 2] = c;
    }
}

extern "C" void kernel_launch(void* const* d_in, const int* in_sizes, int n_in,
                              void* d_out, int out_size) {
    (void)in_sizes; (void)n_in; (void)out_size;
    const float* om5 = (const float*)d_in[0];   // omegas5 (80,3)
    const float* om6 = (const float*)d_in[1];   // omegas6 (79,3)
    float* out = (float*)d_out;                 // 81 floats
    weno_bs_kernel<<<1, 32>>>(om5, om6, out);
}